// round 15
// baseline (speedup 1.0000x reference)
#include <cuda_runtime.h>

#define QW   12
#define DIMS 4096
#define NT   128
#define V    32

// Layout A: s = (t<<5) | k       (k: s0..4, lane: s5..9, warp bits: s10,11)
// Layout B: s = (t&31) | (k<<5) | ((t>>5)<<10)
// wire j <-> s-bit (11-j).

__device__ __forceinline__ float2 cmulf(float2 a, float2 b) {
    return make_float2(fmaf(a.x, b.x, -a.y * b.y), fmaf(a.x, b.y, a.y * b.x));
}

struct Sm {
    float2 xch[DIMS];        // 32KB exchange / image buffer
    float2 tab[512];
    float2 csT[2][6][12];
    float2 uvT[2][6][12];
    float  aS[2][6][12];
    float  ang[12];
    float  red[48];
    float  cwS[108];
    float  cbS[12];
    float  kinit[32];
};

// asm named barrier (id 1, all 128 threads) — part of the low-register recipe
#define HBAR() asm volatile("bar.sync 1, 128;" ::: "memory")

template<int M>
__device__ __forceinline__ void ry_lift(float2* amp, float2 uv) {
    const float u = uv.x, v = uv.y;
#pragma unroll
    for (int k = 0; k < V; k++) {
        if (!(k & M)) {
            float2 a = amp[k], b = amp[k | M];
            a.x = fmaf(u, b.x, a.x); a.y = fmaf(u, b.y, a.y);
            b.x = fmaf(v, a.x, b.x); b.y = fmaf(v, a.y, b.y);
            a.x = fmaf(u, b.x, a.x); a.y = fmaf(u, b.y, a.y);
            amp[k] = a; amp[k | M] = b;
        }
    }
}

__device__ __forceinline__ void reduce12(Sm& sm, float* part, int t, int lane,
                                         float scale, bool addBias) {
#pragma unroll
    for (int j = 0; j < QW; j++) {
        float v = part[j];
        v += __shfl_down_sync(0xffffffffu, v, 16);
        v += __shfl_down_sync(0xffffffffu, v, 8);
        v += __shfl_down_sync(0xffffffffu, v, 4);
        v += __shfl_down_sync(0xffffffffu, v, 2);
        v += __shfl_down_sync(0xffffffffu, v, 1);
        if (lane == 0) sm.red[(t >> 5) * QW + j] = v;
    }
    HBAR();
    if (t < QW) {
        float v = sm.red[t] + sm.red[QW + t] + sm.red[2 * QW + t] + sm.red[3 * QW + t];
        v *= scale;
        if (addBias) v += sm.cbS[t];
        sm.ang[t] = v;
    }
    HBAR();
}

__global__ void __launch_bounds__(NT, 3) qiddm_kernel(
    const float* __restrict__ x, const float* __restrict__ conv_w,
    const float* __restrict__ conv_b, const float* __restrict__ w1,
    const float* __restrict__ lin_w, const float* __restrict__ lin_b,
    float* __restrict__ out)
{
    extern __shared__ char smraw[];
    Sm& sm = *reinterpret_cast<Sm*>(smraw);
    const int t    = threadIdx.x;
    const int lane = t & 31;
    const int wh   = (t >> 5) << 5;
    const int b    = blockIdx.x;
    float2* xc = sm.xch;

    // ---------------- weight tables ----------------
    for (int idx = t; idx < 144; idx += NT) {
        int n = idx / 72, r = idx % 72, g = r / 12, w = r % 12;
        int i = g >> 1, l = g & 1;
        int base = (((n * 3 + i) * 2 + l) * 12 + w) * 3;
        float th = w1[base + 1];
        float sv, cv; __sincosf(0.5f * th, &sv, &cv);
        sm.csT[n][g][w] = make_float2(cv, sv);
        sm.uvT[n][g][w] = make_float2(-__tanf(0.25f * th), sv);
        float a = w1[base + 0];
        if (g > 0) {
            int ip = (g - 1) >> 1, lp = (g - 1) & 1;
            a += w1[(((n * 3 + ip) * 2 + lp) * 12 + w) * 3 + 2];
        }
        sm.aS[n][g][w] = a;
    }
    if (t < 108) sm.cwS[t] = conv_w[t];
    if (t < 12)  sm.cbS[t] = conv_b[t];

    float* img = (float*)xc;
    const float* xb = x + (size_t)b * 1024;
    for (int i = t; i < 1024; i += NT) img[i] = xb[i];
    __syncthreads();

    // ---------------- conv 3x3 s2 p1 + global avg pool ----------------
    {
        float acc[QW];
#pragma unroll
        for (int c = 0; c < QW; c++) acc[c] = 0.f;
        for (int pos = t; pos < 256; pos += NT) {
            int oh = pos >> 4, ow = pos & 15;
#pragma unroll
            for (int kh = 0; kh < 3; kh++) {
                int r2 = 2 * oh + kh - 1;
                if ((unsigned)r2 < 32u) {
#pragma unroll
                    for (int kw = 0; kw < 3; kw++) {
                        int c2 = 2 * ow + kw - 1;
                        if ((unsigned)c2 < 32u) {
                            float v = img[r2 * 32 + c2];
#pragma unroll
                            for (int c = 0; c < QW; c++)
                                acc[c] = fmaf(sm.cwS[c * 9 + kh * 3 + kw], v, acc[c]);
                        }
                    }
                }
            }
        }
        HBAR();
        reduce12(sm, acc, t, lane, 1.f / 256.f, true);
    }

    // ---------------- circuit blocks ----------------
    float2 amp[V];
    for (int n = 0; n < 2; n++) {
        // g=0 skipped: diag on |0> = global phase; 12 RYs on |0> = real product state (layout A)
        const float2* cs0 = sm.csT[n][0];
        if (t < 32) {
            float p = 1.f;
#pragma unroll
            for (int i = 0; i < 5; i++) p *= ((t >> i) & 1) ? cs0[11 - i].y : cs0[11 - i].x;
            sm.kinit[t] = p;
        }
        HBAR();
        float tpp = 1.f;
#pragma unroll
        for (int i = 0; i < 7; i++) tpp *= ((t >> i) & 1) ? cs0[6 - i].y : cs0[6 - i].x;
#pragma unroll
        for (int k = 0; k < V; k++) amp[k] = make_float2(tpp * sm.kinit[k], 0.f);

        for (int g = 1; g < 6; g++) {
            const bool layA = (g & 1);           // diag layout: A for g odd, B for g even
            const int  r    = layA ? 1 : 2;      // CZ ring range of previous sublayer
            const bool addI = ((g & 1) == 0);    // enc folded at g = 2, 4
            const float* aSp = sm.aS[n][g];
            const float* angp = sm.ang;

            // ---- build sign-folded diag table: k = t&31 fixed -> ONE sincos ----
            {
                const int k  = t & 31;
                const int v0 = t >> 5;
                float ph = 0.f;
#pragma unroll
                for (int i = 0; i < 5; i++) {
                    int w = layA ? (11 - i) : (6 - i);
                    float a = aSp[w] + (addI ? angp[w] : 0.f);
                    ph += a * ((float)((k >> i) & 1) - 0.5f);
                }
                float sv, cv; __sincosf(ph, &sv, &cv);
                if (r == 1) {   // 128 entries: v = v0
                    int v = v0;
                    int par = __popc(k & (k >> 1) & 0xF) ^ ((v & (k >> 4)) & 1) ^ (((v >> 1) & k) & 1);
                    float sg = (par & 1) ? -1.f : 1.f;
                    sm.tab[v * 32 + k] = make_float2(cv * sg, sv * sg);
                } else {        // 512 entries: v = v0 + 4j
#pragma unroll
                    for (int j = 0; j < 4; j++) {
                        int v = v0 + 4 * j;
                        int par = __popc(k & (k >> 2) & 0x7) ^ ((v & k) & 1) ^ (((v >> 1) & (k >> 1)) & 1)
                                ^ (((v >> 2) & (k >> 3)) & 1) ^ (((v >> 3) & (k >> 4)) & 1);
                        float sg = (par & 1) ? -1.f : 1.f;
                        sm.tab[v * 32 + k] = make_float2(cv * sg, sv * sg);
                    }
                }
            }

            // ---- per-thread phase + CZ t-internal sign + variant index ----
            float pt = 0.f;
            int ptpar, vv;
            if (layA) {
#pragma unroll
                for (int i = 0; i < 7; i++)
                    pt += (aSp[6 - i] + (addI ? angp[6 - i] : 0.f)) * ((float)((t >> i) & 1) - 0.5f);
                ptpar = __popc(t & (t >> 1) & 0x3F);
                vv    = (t & 1) | (((t >> 6) & 1) << 1);
            } else {
#pragma unroll
                for (int i = 0; i < 5; i++)
                    pt += (aSp[11 - i] + (addI ? angp[11 - i] : 0.f)) * ((float)((t >> i) & 1) - 0.5f);
                pt += (aSp[1] + (addI ? angp[1] : 0.f)) * ((float)((t >> 5) & 1) - 0.5f);
                pt += (aSp[0] + (addI ? angp[0] : 0.f)) * ((float)((t >> 6) & 1) - 0.5f);
                ptpar = __popc(t & (t >> 2) & 0x7) ^ (((t >> 5) & t) & 1) ^ (((t >> 6) & (t >> 1)) & 1);
                vv    = ((t >> 3) & 1) | (((t >> 4) & 1) << 1) | (((t >> 5) & 1) << 2) | (((t >> 6) & 1) << 3);
            }
            float sv, cv; __sincosf(pt, &sv, &cv);
            if (ptpar & 1) { sv = -sv; cv = -cv; }
            const float2 et = make_float2(cv, sv);
            HBAR();   // sync1: tab ready; fences prev radix reads vs this group's transpose stores

            // ---- apply diagonal ----
            const float2* tb = &sm.tab[vv << 5];
            if (g == 1) {  // state still real after product init
#pragma unroll
                for (int k = 0; k < V; k++) {
                    float2 d = cmulf(et, tb[k]);
                    amp[k] = make_float2(amp[k].x * d.x, amp[k].x * d.y);
                }
            } else {
#pragma unroll
                for (int k = 0; k < V; k++) amp[k] = cmulf(amp[k], cmulf(et, tb[k]));
            }

            // ---- locals set 1 (current k-bits) ----
            const float2* uv = sm.uvT[n][g];
            if (layA) {
                ry_lift<1 >(amp, uv[11]); ry_lift<2 >(amp, uv[10]); ry_lift<4 >(amp, uv[9]);
                ry_lift<8 >(amp, uv[8]);  ry_lift<16>(amp, uv[7]);
            } else {
                ry_lift<1 >(amp, uv[6]);  ry_lift<2 >(amp, uv[5]);  ry_lift<4 >(amp, uv[4]);
                ry_lift<8 >(amp, uv[3]);  ry_lift<16>(amp, uv[2]);
            }

            // ---- intra-warp transpose: swap k-bits <-> lane-bits (syncwarp) ----
            if (layA) {  // A -> B
#pragma unroll
                for (int k = 0; k < V; k++) xc[t * 32 + (k ^ lane)] = amp[k];
                __syncwarp();
#pragma unroll
                for (int k = 0; k < V; k++) amp[k] = xc[(k + wh) * 32 + (lane ^ k)];
            } else {     // B -> A
#pragma unroll
                for (int k = 0; k < V; k++) xc[(k + wh) * 32 + (lane ^ k)] = amp[k];
                __syncwarp();
#pragma unroll
                for (int k = 0; k < V; k++) amp[k] = xc[t * 32 + (k ^ lane)];
            }
            __syncwarp();

            // ---- locals set 2 (new k-bits) ----
            if (layA) {
                ry_lift<1 >(amp, uv[6]);  ry_lift<2 >(amp, uv[5]);  ry_lift<4 >(amp, uv[4]);
                ry_lift<8 >(amp, uv[3]);  ry_lift<16>(amp, uv[2]);
            } else {
                ry_lift<1 >(amp, uv[11]); ry_lift<2 >(amp, uv[10]); ry_lift<4 >(amp, uv[9]);
                ry_lift<8 >(amp, uv[8]);  ry_lift<16>(amp, uv[7]);
            }

            // ---- fused radix-4 warp gate (s10 = wire 1, s11 = wire 0) ----
            {
                const float2 cA = sm.csT[n][g][1];
                const float2 cB = sm.csT[n][g][0];
                const float s1e = (t & 32) ? cA.y : -cA.y;
                const float s2e = (t & 64) ? cB.y : -cB.y;
                const float wS  = cA.x * cB.x;
                const float wA  = s1e * cB.x;
                const float wB  = cA.x * s2e;
                const float wC  = s1e * s2e;
                const int tA = t ^ 32, tB = t ^ 64, tC = t ^ 96;
                // CRITICAL: all warps must finish their transpose loads before any
                // warp's radix stores overwrite those tile regions (cross-warp).
                HBAR();   // syncA
#pragma unroll
                for (int k = 0; k < V; k++) xc[k * NT + t] = amp[k];
                HBAR();   // sync2: all warps' radix stores visible
#pragma unroll
                for (int k = 0; k < V; k++) {
                    float2 o1 = xc[k * NT + tA];
                    float2 o2 = xc[k * NT + tB];
                    float2 o3 = xc[k * NT + tC];
                    float ax = wS * amp[k].x, ay = wS * amp[k].y;
                    ax = fmaf(wA, o1.x, ax); ay = fmaf(wA, o1.y, ay);
                    ax = fmaf(wB, o2.x, ax); ay = fmaf(wB, o2.y, ay);
                    ax = fmaf(wC, o3.x, ax); ay = fmaf(wC, o3.y, ay);
                    amp[k] = make_float2(ax, ay);
                }
            }
        }

        // ---- measurement (state in layout B; trailing diag/CZ drop out) ----
        {
            float S = 0.f, q0 = 0.f, q1 = 0.f, q2 = 0.f, q3 = 0.f, q4 = 0.f;
#pragma unroll
            for (int k = 0; k < V; k++) {
                float pr = fmaf(amp[k].x, amp[k].x, amp[k].y * amp[k].y);
                S += pr;
                q0 += (k & 1)  ? -pr : pr;
                q1 += (k & 2)  ? -pr : pr;
                q2 += (k & 4)  ? -pr : pr;
                q3 += (k & 8)  ? -pr : pr;
                q4 += (k & 16) ? -pr : pr;
            }
            float part[QW];
            part[6] = q0; part[5] = q1; part[4] = q2; part[3] = q3; part[2] = q4;
#pragma unroll
            for (int i = 0; i < 5; i++) part[11 - i] = ((t >> i) & 1) ? -S : S;
            part[1] = ((t >> 5) & 1) ? -S : S;
            part[0] = ((t >> 6) & 1) ? -S : S;
            HBAR();
            reduce12(sm, part, t, lane, 1.f, false);
        }
    }

    // ---------------- linear head ----------------
    for (int m = t; m < 1024; m += NT) {
        float acc = lin_b[m];
#pragma unroll
        for (int j = 0; j < QW; j++) acc = fmaf(sm.ang[j], lin_w[m * 12 + j], acc);
        out[(size_t)b * 1024 + m] = acc;
    }
}

extern "C" void kernel_launch(void* const* d_in, const int* in_sizes, int n_in,
                              void* d_out, int out_size) {
    const float* x      = (const float*)d_in[0];
    const float* conv_w = (const float*)d_in[1];
    const float* conv_b = (const float*)d_in[2];
    const float* w1     = (const float*)d_in[3];
    const float* lin_w  = (const float*)d_in[4];
    const float* lin_b  = (const float*)d_in[5];
    float* out = (float*)d_out;
    int B = in_sizes[0] / 1024;
    cudaFuncSetAttribute(qiddm_kernel, cudaFuncAttributeMaxDynamicSharedMemorySize,
                         (int)sizeof(Sm));
    qiddm_kernel<<<B, NT, sizeof(Sm)>>>(x, conv_w, conv_b, w1, lin_w, lin_b, out);
}

// round 16
// speedup vs baseline: 1.0936x; 1.0936x over previous
#include <cuda_runtime.h>

#define QW   12
#define DIMS 4096
#define NT   128
#define V    32

// Layout A: s = (t<<5) | k       (k: s0..4, lane: s5..9, warp bits: s10,11)
// Layout B: s = (t&31) | (k<<5) | ((t>>5)<<10)
// wire j <-> s-bit (11-j).  Warp bits (s10,s11) = wires 1,0 in BOTH layouts.
// Per group: diag -> 5 local gates -> ONE store (transpose positions) -> HBAR ->
// merged transpose+radix-4 read (4 rows, radix over warp bits) -> 5 local gates.

__device__ __forceinline__ float2 cmulf(float2 a, float2 b) {
    return make_float2(fmaf(a.x, b.x, -a.y * b.y), fmaf(a.x, b.y, a.y * b.x));
}

struct Sm {
    float2 xch[DIMS];        // 32KB exchange / image buffer
    float2 tab[512];
    float2 csT[2][6][12];
    float2 uvT[2][6][12];
    float  aS[2][6][12];
    float  ang[12];
    float  red[48];
    float  cwS[108];
    float  cbS[12];
    float  kinit[32];
};

// asm named barrier (id 1, all 128 threads) — part of the low-register recipe
#define HBAR() asm volatile("bar.sync 1, 128;" ::: "memory")

template<int M>
__device__ __forceinline__ void ry_lift(float2* amp, float2 uv) {
    const float u = uv.x, v = uv.y;
#pragma unroll
    for (int k = 0; k < V; k++) {
        if (!(k & M)) {
            float2 a = amp[k], b = amp[k | M];
            a.x = fmaf(u, b.x, a.x); a.y = fmaf(u, b.y, a.y);
            b.x = fmaf(v, a.x, b.x); b.y = fmaf(v, a.y, b.y);
            a.x = fmaf(u, b.x, a.x); a.y = fmaf(u, b.y, a.y);
            amp[k] = a; amp[k | M] = b;
        }
    }
}

__device__ __forceinline__ void reduce12(Sm& sm, float* part, int t, int lane,
                                         float scale, bool addBias) {
#pragma unroll
    for (int j = 0; j < QW; j++) {
        float v = part[j];
        v += __shfl_down_sync(0xffffffffu, v, 16);
        v += __shfl_down_sync(0xffffffffu, v, 8);
        v += __shfl_down_sync(0xffffffffu, v, 4);
        v += __shfl_down_sync(0xffffffffu, v, 2);
        v += __shfl_down_sync(0xffffffffu, v, 1);
        if (lane == 0) sm.red[(t >> 5) * QW + j] = v;
    }
    HBAR();
    if (t < QW) {
        float v = sm.red[t] + sm.red[QW + t] + sm.red[2 * QW + t] + sm.red[3 * QW + t];
        v *= scale;
        if (addBias) v += sm.cbS[t];
        sm.ang[t] = v;
    }
    HBAR();
}

__global__ void __launch_bounds__(NT, 3) qiddm_kernel(
    const float* __restrict__ x, const float* __restrict__ conv_w,
    const float* __restrict__ conv_b, const float* __restrict__ w1,
    const float* __restrict__ lin_w, const float* __restrict__ lin_b,
    float* __restrict__ out)
{
    extern __shared__ char smraw[];
    Sm& sm = *reinterpret_cast<Sm*>(smraw);
    const int t    = threadIdx.x;
    const int lane = t & 31;
    const int wh   = (t >> 5) << 5;
    const int b    = blockIdx.x;
    float2* xc = sm.xch;

    // ---------------- weight tables ----------------
    for (int idx = t; idx < 144; idx += NT) {
        int n = idx / 72, r = idx % 72, g = r / 12, w = r % 12;
        int i = g >> 1, l = g & 1;
        int base = (((n * 3 + i) * 2 + l) * 12 + w) * 3;
        float th = w1[base + 1];
        float sv, cv; __sincosf(0.5f * th, &sv, &cv);
        sm.csT[n][g][w] = make_float2(cv, sv);
        sm.uvT[n][g][w] = make_float2(-__tanf(0.25f * th), sv);
        float a = w1[base + 0];
        if (g > 0) {
            int ip = (g - 1) >> 1, lp = (g - 1) & 1;
            a += w1[(((n * 3 + ip) * 2 + lp) * 12 + w) * 3 + 2];
        }
        sm.aS[n][g][w] = a;
    }
    if (t < 108) sm.cwS[t] = conv_w[t];
    if (t < 12)  sm.cbS[t] = conv_b[t];

    float* img = (float*)xc;
    const float* xb = x + (size_t)b * 1024;
    for (int i = t; i < 1024; i += NT) img[i] = xb[i];
    __syncthreads();

    // ---------------- conv 3x3 s2 p1 + global avg pool ----------------
    {
        float acc[QW];
#pragma unroll
        for (int c = 0; c < QW; c++) acc[c] = 0.f;
        for (int pos = t; pos < 256; pos += NT) {
            int oh = pos >> 4, ow = pos & 15;
#pragma unroll
            for (int kh = 0; kh < 3; kh++) {
                int r2 = 2 * oh + kh - 1;
                if ((unsigned)r2 < 32u) {
#pragma unroll
                    for (int kw = 0; kw < 3; kw++) {
                        int c2 = 2 * ow + kw - 1;
                        if ((unsigned)c2 < 32u) {
                            float v = img[r2 * 32 + c2];
#pragma unroll
                            for (int c = 0; c < QW; c++)
                                acc[c] = fmaf(sm.cwS[c * 9 + kh * 3 + kw], v, acc[c]);
                        }
                    }
                }
            }
        }
        HBAR();
        reduce12(sm, acc, t, lane, 1.f / 256.f, true);
    }

    // ---------------- circuit blocks ----------------
    float2 amp[V];
    for (int n = 0; n < 2; n++) {
        // g=0 skipped: diag on |0> = global phase; 12 RYs on |0> = real product state (layout A)
        const float2* cs0 = sm.csT[n][0];
        if (t < 32) {
            float p = 1.f;
#pragma unroll
            for (int i = 0; i < 5; i++) p *= ((t >> i) & 1) ? cs0[11 - i].y : cs0[11 - i].x;
            sm.kinit[t] = p;
        }
        HBAR();
        float tpp = 1.f;
#pragma unroll
        for (int i = 0; i < 7; i++) tpp *= ((t >> i) & 1) ? cs0[6 - i].y : cs0[6 - i].x;
#pragma unroll
        for (int k = 0; k < V; k++) amp[k] = make_float2(tpp * sm.kinit[k], 0.f);

        for (int g = 1; g < 6; g++) {
            const bool layA = (g & 1);           // diag layout: A for g odd, B for g even
            const int  r    = layA ? 1 : 2;      // CZ ring range of previous sublayer
            const bool addI = ((g & 1) == 0);    // enc folded at g = 2, 4
            const float* aSp = sm.aS[n][g];
            const float* angp = sm.ang;

            // ---- build sign-folded diag table: k = t&31 fixed -> ONE sincos ----
            {
                const int k  = t & 31;
                const int v0 = t >> 5;
                float ph = 0.f;
#pragma unroll
                for (int i = 0; i < 5; i++) {
                    int w = layA ? (11 - i) : (6 - i);
                    float a = aSp[w] + (addI ? angp[w] : 0.f);
                    ph += a * ((float)((k >> i) & 1) - 0.5f);
                }
                float sv, cv; __sincosf(ph, &sv, &cv);
                if (r == 1) {   // 128 entries: v = v0
                    int v = v0;
                    int par = __popc(k & (k >> 1) & 0xF) ^ ((v & (k >> 4)) & 1) ^ (((v >> 1) & k) & 1);
                    float sg = (par & 1) ? -1.f : 1.f;
                    sm.tab[v * 32 + k] = make_float2(cv * sg, sv * sg);
                } else {        // 512 entries: v = v0 + 4j
#pragma unroll
                    for (int j = 0; j < 4; j++) {
                        int v = v0 + 4 * j;
                        int par = __popc(k & (k >> 2) & 0x7) ^ ((v & k) & 1) ^ (((v >> 1) & (k >> 1)) & 1)
                                ^ (((v >> 2) & (k >> 3)) & 1) ^ (((v >> 3) & (k >> 4)) & 1);
                        float sg = (par & 1) ? -1.f : 1.f;
                        sm.tab[v * 32 + k] = make_float2(cv * sg, sv * sg);
                    }
                }
            }

            // ---- per-thread phase + CZ t-internal sign + variant index ----
            float pt = 0.f;
            int ptpar, vv;
            if (layA) {
#pragma unroll
                for (int i = 0; i < 7; i++)
                    pt += (aSp[6 - i] + (addI ? angp[6 - i] : 0.f)) * ((float)((t >> i) & 1) - 0.5f);
                ptpar = __popc(t & (t >> 1) & 0x3F);
                vv    = (t & 1) | (((t >> 6) & 1) << 1);
            } else {
#pragma unroll
                for (int i = 0; i < 5; i++)
                    pt += (aSp[11 - i] + (addI ? angp[11 - i] : 0.f)) * ((float)((t >> i) & 1) - 0.5f);
                pt += (aSp[1] + (addI ? angp[1] : 0.f)) * ((float)((t >> 5) & 1) - 0.5f);
                pt += (aSp[0] + (addI ? angp[0] : 0.f)) * ((float)((t >> 6) & 1) - 0.5f);
                ptpar = __popc(t & (t >> 2) & 0x7) ^ (((t >> 5) & t) & 1) ^ (((t >> 6) & (t >> 1)) & 1);
                vv    = ((t >> 3) & 1) | (((t >> 4) & 1) << 1) | (((t >> 5) & 1) << 2) | (((t >> 6) & 1) << 3);
            }
            float sv, cv; __sincosf(pt, &sv, &cv);
            if (ptpar & 1) { sv = -sv; cv = -cv; }
            const float2 et = make_float2(cv, sv);
            HBAR();   // sync1: tab ready; fences prev group's merged reads vs this group's stores

            // ---- apply diagonal ----
            const float2* tb = &sm.tab[vv << 5];
            if (g == 1) {  // state still real after product init
#pragma unroll
                for (int k = 0; k < V; k++) {
                    float2 d = cmulf(et, tb[k]);
                    amp[k] = make_float2(amp[k].x * d.x, amp[k].x * d.y);
                }
            } else {
#pragma unroll
                for (int k = 0; k < V; k++) amp[k] = cmulf(amp[k], cmulf(et, tb[k]));
            }

            // ---- locals set 1 (current k-bits) ----
            const float2* uv = sm.uvT[n][g];
            if (layA) {
                ry_lift<1 >(amp, uv[11]); ry_lift<2 >(amp, uv[10]); ry_lift<4 >(amp, uv[9]);
                ry_lift<8 >(amp, uv[8]);  ry_lift<16>(amp, uv[7]);
            } else {
                ry_lift<1 >(amp, uv[6]);  ry_lift<2 >(amp, uv[5]);  ry_lift<4 >(amp, uv[4]);
                ry_lift<8 >(amp, uv[3]);  ry_lift<16>(amp, uv[2]);
            }

            // ---- ONE store at transpose positions ----
            if (layA) {  // A positions, own row t
#pragma unroll
                for (int k = 0; k < V; k++) xc[t * 32 + (k ^ lane)] = amp[k];
            } else {     // B positions
#pragma unroll
                for (int k = 0; k < V; k++) xc[(k + wh) * 32 + (lane ^ k)] = amp[k];
            }
            HBAR();      // sync2: all warps' stores visible

            // ---- merged transpose + radix-4 warp-bit gate (4-row read) ----
            {
                const float2 cA = sm.csT[n][g][1];   // s10 gate (wire 1)
                const float2 cB = sm.csT[n][g][0];   // s11 gate (wire 0)
                const float s1e = (t & 32) ? cA.y : -cA.y;
                const float s2e = (t & 64) ? cB.y : -cB.y;
                const float C0 = cA.x * cB.x;    // source w' = w      (j=0)
                const float C1 = s1e * cB.x;     // source w' = w^1    (j=1, s10 flip)
                const float C2 = cA.x * s2e;     // source w' = w^2    (j=2, s11 flip)
                const float C3 = s1e * s2e;      // source w' = w^3
                if (layA) {
                    // load into layout B: rows k + 32*(w^j), col lane^k
                    const int rw = wh;   // w<<5
#pragma unroll
                    for (int k = 0; k < V; k++) {
                        const int col = lane ^ k;
                        float2 o0 = xc[((rw ^  0) + k) * 32 + col];
                        float2 o1 = xc[((rw ^ 32) + k) * 32 + col];
                        float2 o2 = xc[((rw ^ 64) + k) * 32 + col];
                        float2 o3 = xc[((rw ^ 96) + k) * 32 + col];
                        float ax = C0 * o0.x, ay = C0 * o0.y;
                        ax = fmaf(C1, o1.x, ax); ay = fmaf(C1, o1.y, ay);
                        ax = fmaf(C2, o2.x, ax); ay = fmaf(C2, o2.y, ay);
                        ax = fmaf(C3, o3.x, ax); ay = fmaf(C3, o3.y, ay);
                        amp[k] = make_float2(ax, ay);
                    }
                } else {
                    // load into layout A: rows t ^ (j<<5), col k^lane
                    const int r0 = t * 32, r1 = (t ^ 32) * 32, r2 = (t ^ 64) * 32, r3 = (t ^ 96) * 32;
#pragma unroll
                    for (int k = 0; k < V; k++) {
                        const int col = k ^ lane;
                        float2 o0 = xc[r0 + col];
                        float2 o1 = xc[r1 + col];
                        float2 o2 = xc[r2 + col];
                        float2 o3 = xc[r3 + col];
                        float ax = C0 * o0.x, ay = C0 * o0.y;
                        ax = fmaf(C1, o1.x, ax); ay = fmaf(C1, o1.y, ay);
                        ax = fmaf(C2, o2.x, ax); ay = fmaf(C2, o2.y, ay);
                        ax = fmaf(C3, o3.x, ax); ay = fmaf(C3, o3.y, ay);
                        amp[k] = make_float2(ax, ay);
                    }
                }
            }

            // ---- locals set 2 (new k-bits) ----
            if (layA) {
                ry_lift<1 >(amp, uv[6]);  ry_lift<2 >(amp, uv[5]);  ry_lift<4 >(amp, uv[4]);
                ry_lift<8 >(amp, uv[3]);  ry_lift<16>(amp, uv[2]);
            } else {
                ry_lift<1 >(amp, uv[11]); ry_lift<2 >(amp, uv[10]); ry_lift<4 >(amp, uv[9]);
                ry_lift<8 >(amp, uv[8]);  ry_lift<16>(amp, uv[7]);
            }
        }

        // ---- measurement (state in layout B; trailing diag/CZ drop out) ----
        {
            float S = 0.f, q0 = 0.f, q1 = 0.f, q2 = 0.f, q3 = 0.f, q4 = 0.f;
#pragma unroll
            for (int k = 0; k < V; k++) {
                float pr = fmaf(amp[k].x, amp[k].x, amp[k].y * amp[k].y);
                S += pr;
                q0 += (k & 1)  ? -pr : pr;
                q1 += (k & 2)  ? -pr : pr;
                q2 += (k & 4)  ? -pr : pr;
                q3 += (k & 8)  ? -pr : pr;
                q4 += (k & 16) ? -pr : pr;
            }
            float part[QW];
            part[6] = q0; part[5] = q1; part[4] = q2; part[3] = q3; part[2] = q4;
#pragma unroll
            for (int i = 0; i < 5; i++) part[11 - i] = ((t >> i) & 1) ? -S : S;
            part[1] = ((t >> 5) & 1) ? -S : S;
            part[0] = ((t >> 6) & 1) ? -S : S;
            HBAR();
            reduce12(sm, part, t, lane, 1.f, false);
        }
    }

    // ---------------- linear head ----------------
    for (int m = t; m < 1024; m += NT) {
        float acc = lin_b[m];
#pragma unroll
        for (int j = 0; j < QW; j++) acc = fmaf(sm.ang[j], lin_w[m * 12 + j], acc);
        out[(size_t)b * 1024 + m] = acc;
    }
}

extern "C" void kernel_launch(void* const* d_in, const int* in_sizes, int n_in,
                              void* d_out, int out_size) {
    const float* x      = (const float*)d_in[0];
    const float* conv_w = (const float*)d_in[1];
    const float* conv_b = (const float*)d_in[2];
    const float* w1     = (const float*)d_in[3];
    const float* lin_w  = (const float*)d_in[4];
    const float* lin_b  = (const float*)d_in[5];
    float* out = (float*)d_out;
    int B = in_sizes[0] / 1024;
    cudaFuncSetAttribute(qiddm_kernel, cudaFuncAttributeMaxDynamicSharedMemorySize,
                         (int)sizeof(Sm));
    qiddm_kernel<<<B, NT, sizeof(Sm)>>>(x, conv_w, conv_b, w1, lin_w, lin_b, out);
}

// round 17
// speedup vs baseline: 1.1210x; 1.0251x over previous
#include <cuda_runtime.h>

#define QW   12
#define DIMS 4096
#define NT   128
#define V    32

// Layout A: s = (t<<5) | k ; Layout B: s = (t&31) | (k<<5) | ((t>>5)<<10).
// wire j <-> s-bit (11-j).  Warp bits (s10,s11) = wires 1,0 in BOTH layouts.
// Exchange (both parities): scatter-store at destination positions
//   xc[(k + wh)*32 + col], col = ((lane>>1 ^ (k&15))<<1) | (lane&1)
// then gather-contiguous float4 read rows t^(j<<5) with radix-4 over warp bits.

__device__ __forceinline__ float2 cmulf(float2 a, float2 b) {
    return make_float2(fmaf(a.x, b.x, -a.y * b.y), fmaf(a.x, b.y, a.y * b.x));
}

struct Sm {
    float2 xch[DIMS];        // 32KB exchange / image buffer
    float2 tab[512];
    float2 csT[2][6][12];
    float2 uvT[2][6][12];
    float  aS[2][6][12];
    float  ang[12];
    float  red[48];
    float  cwS[108];
    float  cbS[12];
    float  kinit[32];
};

// asm named barrier (id 1, all 128 threads) — part of the low-register recipe
#define HBAR() asm volatile("bar.sync 1, 128;" ::: "memory")

template<int M>
__device__ __forceinline__ void ry_lift(float2* amp, float2 uv) {
    const float u = uv.x, v = uv.y;
#pragma unroll
    for (int k = 0; k < V; k++) {
        if (!(k & M)) {
            float2 a = amp[k], b = amp[k | M];
            a.x = fmaf(u, b.x, a.x); a.y = fmaf(u, b.y, a.y);
            b.x = fmaf(v, a.x, b.x); b.y = fmaf(v, a.y, b.y);
            a.x = fmaf(u, b.x, a.x); a.y = fmaf(u, b.y, a.y);
            amp[k] = a; amp[k | M] = b;
        }
    }
}

__device__ __forceinline__ void reduce12(Sm& sm, float* part, int t, int lane,
                                         float scale, bool addBias) {
#pragma unroll
    for (int j = 0; j < QW; j++) {
        float v = part[j];
        v += __shfl_down_sync(0xffffffffu, v, 16);
        v += __shfl_down_sync(0xffffffffu, v, 8);
        v += __shfl_down_sync(0xffffffffu, v, 4);
        v += __shfl_down_sync(0xffffffffu, v, 2);
        v += __shfl_down_sync(0xffffffffu, v, 1);
        if (lane == 0) sm.red[(t >> 5) * QW + j] = v;
    }
    HBAR();
    if (t < QW) {
        float v = sm.red[t] + sm.red[QW + t] + sm.red[2 * QW + t] + sm.red[3 * QW + t];
        v *= scale;
        if (addBias) v += sm.cbS[t];
        sm.ang[t] = v;
    }
    HBAR();
}

__global__ void __launch_bounds__(NT, 3) qiddm_kernel(
    const float* __restrict__ x, const float* __restrict__ conv_w,
    const float* __restrict__ conv_b, const float* __restrict__ w1,
    const float* __restrict__ lin_w, const float* __restrict__ lin_b,
    float* __restrict__ out)
{
    extern __shared__ char smraw[];
    Sm& sm = *reinterpret_cast<Sm*>(smraw);
    const int t    = threadIdx.x;
    const int lane = t & 31;
    const int wh   = (t >> 5) << 5;
    const int b    = blockIdx.x;
    float2* xc = sm.xch;

    // ---------------- weight tables ----------------
    for (int idx = t; idx < 144; idx += NT) {
        int n = idx / 72, r = idx % 72, g = r / 12, w = r % 12;
        int i = g >> 1, l = g & 1;
        int base = (((n * 3 + i) * 2 + l) * 12 + w) * 3;
        float th = w1[base + 1];
        float sv, cv; __sincosf(0.5f * th, &sv, &cv);
        sm.csT[n][g][w] = make_float2(cv, sv);
        sm.uvT[n][g][w] = make_float2(-__tanf(0.25f * th), sv);
        float a = w1[base + 0];
        if (g > 0) {
            int ip = (g - 1) >> 1, lp = (g - 1) & 1;
            a += w1[(((n * 3 + ip) * 2 + lp) * 12 + w) * 3 + 2];
        }
        sm.aS[n][g][w] = a;
    }
    if (t < 108) sm.cwS[t] = conv_w[t];
    if (t < 12)  sm.cbS[t] = conv_b[t];

    float* img = (float*)xc;
    const float* xb = x + (size_t)b * 1024;
    for (int i = t; i < 1024; i += NT) img[i] = xb[i];
    __syncthreads();

    // ---------------- conv 3x3 s2 p1 + global avg pool ----------------
    {
        float acc[QW];
#pragma unroll
        for (int c = 0; c < QW; c++) acc[c] = 0.f;
        for (int pos = t; pos < 256; pos += NT) {
            int oh = pos >> 4, ow = pos & 15;
#pragma unroll
            for (int kh = 0; kh < 3; kh++) {
                int r2 = 2 * oh + kh - 1;
                if ((unsigned)r2 < 32u) {
#pragma unroll
                    for (int kw = 0; kw < 3; kw++) {
                        int c2 = 2 * ow + kw - 1;
                        if ((unsigned)c2 < 32u) {
                            float v = img[r2 * 32 + c2];
#pragma unroll
                            for (int c = 0; c < QW; c++)
                                acc[c] = fmaf(sm.cwS[c * 9 + kh * 3 + kw], v, acc[c]);
                        }
                    }
                }
            }
        }
        HBAR();
        reduce12(sm, acc, t, lane, 1.f / 256.f, true);
    }

    // ---------------- circuit blocks ----------------
    float2 amp[V];
    for (int n = 0; n < 2; n++) {
        // g=0 skipped: diag on |0> = global phase; 12 RYs on |0> = real product state (layout A)
        const float2* cs0 = sm.csT[n][0];
        if (t < 32) {
            float p = 1.f;
#pragma unroll
            for (int i = 0; i < 5; i++) p *= ((t >> i) & 1) ? cs0[11 - i].y : cs0[11 - i].x;
            sm.kinit[t] = p;
        }
        HBAR();
        float tpp = 1.f;
#pragma unroll
        for (int i = 0; i < 7; i++) tpp *= ((t >> i) & 1) ? cs0[6 - i].y : cs0[6 - i].x;
#pragma unroll
        for (int k = 0; k < V; k++) amp[k] = make_float2(tpp * sm.kinit[k], 0.f);

        for (int g = 1; g < 6; g++) {
            const bool layA = (g & 1);           // diag layout: A for g odd, B for g even
            const int  r    = layA ? 1 : 2;      // CZ ring range of previous sublayer
            const bool addI = ((g & 1) == 0);    // enc folded at g = 2, 4
            const float* aSp = sm.aS[n][g];
            const float* angp = sm.ang;

            // ---- build sign-folded diag table: k = t&31 fixed -> ONE sincos ----
            {
                const int k  = t & 31;
                const int v0 = t >> 5;
                float ph = 0.f;
#pragma unroll
                for (int i = 0; i < 5; i++) {
                    int w = layA ? (11 - i) : (6 - i);
                    float a = aSp[w] + (addI ? angp[w] : 0.f);
                    ph += a * ((float)((k >> i) & 1) - 0.5f);
                }
                float sv, cv; __sincosf(ph, &sv, &cv);
                if (r == 1) {   // 128 entries: v = v0
                    int v = v0;
                    int par = __popc(k & (k >> 1) & 0xF) ^ ((v & (k >> 4)) & 1) ^ (((v >> 1) & k) & 1);
                    float sg = (par & 1) ? -1.f : 1.f;
                    sm.tab[v * 32 + k] = make_float2(cv * sg, sv * sg);
                } else {        // 512 entries: v = v0 + 4j
#pragma unroll
                    for (int j = 0; j < 4; j++) {
                        int v = v0 + 4 * j;
                        int par = __popc(k & (k >> 2) & 0x7) ^ ((v & k) & 1) ^ (((v >> 1) & (k >> 1)) & 1)
                                ^ (((v >> 2) & (k >> 3)) & 1) ^ (((v >> 3) & (k >> 4)) & 1);
                        float sg = (par & 1) ? -1.f : 1.f;
                        sm.tab[v * 32 + k] = make_float2(cv * sg, sv * sg);
                    }
                }
            }

            // ---- per-thread phase + CZ t-internal sign + variant index ----
            float pt = 0.f;
            int ptpar, vv;
            if (layA) {
#pragma unroll
                for (int i = 0; i < 7; i++)
                    pt += (aSp[6 - i] + (addI ? angp[6 - i] : 0.f)) * ((float)((t >> i) & 1) - 0.5f);
                ptpar = __popc(t & (t >> 1) & 0x3F);
                vv    = (t & 1) | (((t >> 6) & 1) << 1);
            } else {
#pragma unroll
                for (int i = 0; i < 5; i++)
                    pt += (aSp[11 - i] + (addI ? angp[11 - i] : 0.f)) * ((float)((t >> i) & 1) - 0.5f);
                pt += (aSp[1] + (addI ? angp[1] : 0.f)) * ((float)((t >> 5) & 1) - 0.5f);
                pt += (aSp[0] + (addI ? angp[0] : 0.f)) * ((float)((t >> 6) & 1) - 0.5f);
                ptpar = __popc(t & (t >> 2) & 0x7) ^ (((t >> 5) & t) & 1) ^ (((t >> 6) & (t >> 1)) & 1);
                vv    = ((t >> 3) & 1) | (((t >> 4) & 1) << 1) | (((t >> 5) & 1) << 2) | (((t >> 6) & 1) << 3);
            }
            float sv, cv; __sincosf(pt, &sv, &cv);
            if (ptpar & 1) { sv = -sv; cv = -cv; }
            const float2 et = make_float2(cv, sv);
            HBAR();   // sync1: tab ready; fences prev group's gather reads vs this group's stores

            // ---- apply diagonal (float4 tab loads) ----
            const float4* tb4 = (const float4*)(sm.tab + (vv << 5));
            if (g == 1) {  // state still real after product init
#pragma unroll
                for (int kp = 0; kp < 16; kp++) {
                    float4 tv = tb4[kp];
                    float2 d0 = cmulf(et, make_float2(tv.x, tv.y));
                    float2 d1 = cmulf(et, make_float2(tv.z, tv.w));
                    float a0 = amp[2 * kp].x, a1 = amp[2 * kp + 1].x;
                    amp[2 * kp]     = make_float2(a0 * d0.x, a0 * d0.y);
                    amp[2 * kp + 1] = make_float2(a1 * d1.x, a1 * d1.y);
                }
            } else {
#pragma unroll
                for (int kp = 0; kp < 16; kp++) {
                    float4 tv = tb4[kp];
                    amp[2 * kp]     = cmulf(amp[2 * kp],     cmulf(et, make_float2(tv.x, tv.y)));
                    amp[2 * kp + 1] = cmulf(amp[2 * kp + 1], cmulf(et, make_float2(tv.z, tv.w)));
                }
            }

            // ---- locals set 1 (current k-bits) ----
            const float2* uv = sm.uvT[n][g];
            if (layA) {
                ry_lift<1 >(amp, uv[11]); ry_lift<2 >(amp, uv[10]); ry_lift<4 >(amp, uv[9]);
                ry_lift<8 >(amp, uv[8]);  ry_lift<16>(amp, uv[7]);
            } else {
                ry_lift<1 >(amp, uv[6]);  ry_lift<2 >(amp, uv[5]);  ry_lift<4 >(amp, uv[4]);
                ry_lift<8 >(amp, uv[3]);  ry_lift<16>(amp, uv[2]);
            }

            // ---- scatter store at destination positions (both parities identical) ----
#pragma unroll
            for (int k = 0; k < V; k++) {
                const int col = ((((lane >> 1) ^ k) & 15) << 1) | (lane & 1);
                xc[(k + wh) * 32 + col] = amp[k];
            }
            HBAR();      // sync2: all warps' stores visible

            // ---- merged gather transpose + radix-4 warp-bit gate (float4 reads) ----
            {
                const float2 cA = sm.csT[n][g][1];   // s10 gate (wire 1)
                const float2 cB = sm.csT[n][g][0];   // s11 gate (wire 0)
                const float s1e = (t & 32) ? cA.y : -cA.y;
                const float s2e = (t & 64) ? cB.y : -cB.y;
                const float C0 = cA.x * cB.x;
                const float C1 = s1e * cB.x;
                const float C2 = cA.x * s2e;
                const float C3 = s1e * s2e;
                const float4* xv = (const float4*)xc;
                const int r0 = t * 16, r1 = (t ^ 32) * 16, r2 = (t ^ 64) * 16, r3 = (t ^ 96) * 16;
                const int lh = lane & 15;
#pragma unroll
                for (int kp = 0; kp < 16; kp++) {
                    const int c4 = kp ^ lh;
                    float4 o0 = xv[r0 + c4];
                    float4 o1 = xv[r1 + c4];
                    float4 o2 = xv[r2 + c4];
                    float4 o3 = xv[r3 + c4];
                    float x0 = C0 * o0.x, y0 = C0 * o0.y;
                    x0 = fmaf(C1, o1.x, x0); y0 = fmaf(C1, o1.y, y0);
                    x0 = fmaf(C2, o2.x, x0); y0 = fmaf(C2, o2.y, y0);
                    x0 = fmaf(C3, o3.x, x0); y0 = fmaf(C3, o3.y, y0);
                    float x1 = C0 * o0.z, y1 = C0 * o0.w;
                    x1 = fmaf(C1, o1.z, x1); y1 = fmaf(C1, o1.w, y1);
                    x1 = fmaf(C2, o2.z, x1); y1 = fmaf(C2, o2.w, y1);
                    x1 = fmaf(C3, o3.z, x1); y1 = fmaf(C3, o3.w, y1);
                    amp[2 * kp]     = make_float2(x0, y0);
                    amp[2 * kp + 1] = make_float2(x1, y1);
                }
            }

            // ---- locals set 2 (new k-bits) ----
            if (layA) {
                ry_lift<1 >(amp, uv[6]);  ry_lift<2 >(amp, uv[5]);  ry_lift<4 >(amp, uv[4]);
                ry_lift<8 >(amp, uv[3]);  ry_lift<16>(amp, uv[2]);
            } else {
                ry_lift<1 >(amp, uv[11]); ry_lift<2 >(amp, uv[10]); ry_lift<4 >(amp, uv[9]);
                ry_lift<8 >(amp, uv[8]);  ry_lift<16>(amp, uv[7]);
            }
        }

        // ---- measurement (state in layout B; trailing diag/CZ drop out) ----
        {
            float S = 0.f, q0 = 0.f, q1 = 0.f, q2 = 0.f, q3 = 0.f, q4 = 0.f;
#pragma unroll
            for (int k = 0; k < V; k++) {
                float pr = fmaf(amp[k].x, amp[k].x, amp[k].y * amp[k].y);
                S += pr;
                q0 += (k & 1)  ? -pr : pr;
                q1 += (k & 2)  ? -pr : pr;
                q2 += (k & 4)  ? -pr : pr;
                q3 += (k & 8)  ? -pr : pr;
                q4 += (k & 16) ? -pr : pr;
            }
            float part[QW];
            part[6] = q0; part[5] = q1; part[4] = q2; part[3] = q3; part[2] = q4;
#pragma unroll
            for (int i = 0; i < 5; i++) part[11 - i] = ((t >> i) & 1) ? -S : S;
            part[1] = ((t >> 5) & 1) ? -S : S;
            part[0] = ((t >> 6) & 1) ? -S : S;
            HBAR();
            reduce12(sm, part, t, lane, 1.f, false);
        }
    }

    // ---------------- linear head ----------------
    for (int m = t; m < 1024; m += NT) {
        float acc = lin_b[m];
#pragma unroll
        for (int j = 0; j < QW; j++) acc = fmaf(sm.ang[j], lin_w[m * 12 + j], acc);
        out[(size_t)b * 1024 + m] = acc;
    }
}

extern "C" void kernel_launch(void* const* d_in, const int* in_sizes, int n_in,
                              void* d_out, int out_size) {
    const float* x      = (const float*)d_in[0];
    const float* conv_w = (const float*)d_in[1];
    const float* conv_b = (const float*)d_in[2];
    const float* w1     = (const float*)d_in[3];
    const float* lin_w  = (const float*)d_in[4];
    const float* lin_b  = (const float*)d_in[5];
    float* out = (float*)d_out;
    int B = in_sizes[0] / 1024;
    cudaFuncSetAttribute(qiddm_kernel, cudaFuncAttributeMaxDynamicSharedMemorySize,
                         (int)sizeof(Sm));
    qiddm_kernel<<<B, NT, sizeof(Sm)>>>(x, conv_w, conv_b, w1, lin_w, lin_b, out);
}